// round 15
// baseline (speedup 1.0000x reference)
#include <cuda_runtime.h>
#include <cstdint>
#include <cfloat>

typedef unsigned long long ull;

// Problem constants
#define NB   128
#define NP   8732
#define NC   21
#define TOPK 200
#define NT   640
#define NW   20
#define KPL  14                  // ceil(8732 / 640)
#define NGRP 273                 // ceil(8732 / 32) groups per batch

// Select config
#define BIN0  6016
#define NBIN  128
#define CHCAP 512
#define WANT  384
#define CCAP  200

// key = [monotone score:32][~idx:16][cls:8][0:8]; unsigned MAX == (score desc, idx asc)
__device__ __forceinline__ ull pack_key(float v, unsigned idx, unsigned cls) {
    unsigned bq = __float_as_uint(v);
    bq ^= (unsigned)(((int)bq >> 31) | 0x80000000);
    return ((ull)bq << 32) | ((ull)((~idx) & 0xFFFFu) << 16) | ((ull)cls << 8);
}

#define CP_ASYNC_16(dst_s32, src_g) \
    asm volatile("cp.async.cg.shared.global [%0], [%1], 16;" :: "r"(dst_s32), "l"(src_g))
#define CP_ASYNC_COMMIT() asm volatile("cp.async.commit_group;")
#define CP_ASYNC_WAIT_1() asm volatile("cp.async.wait_group 1;")
#define CP_ASYNC_WAIT_0() asm volatile("cp.async.wait_group 0;")

// ===========================================================================
// Fused kernel: one CTA per batch.
//   Phase P: cp.async double-buffered softmax/argmax -> smem keys + hist.
//   Phase S: threshold + scan-gather + 512-wide sort + deferred decode +
//            20 per-class walks + ordered compaction emit.
// ===========================================================================
// smem layout (bytes)
#define OFF_SKEY   0                       // ull[8736]      69888
#define OFF_CLIST  69888                   // float4[4000]   64000 (stageA[20][688] aliases in phase P)
#define OFF_PFBOX  133888                  // float4[512]     8192
#define OFF_CHA    142080                  // ull[512]        4096  } contiguous 12288B scratch:
#define OFF_CHB    146176                  // ull[1024]       8192  } sort OOB-safe + whist alias
#define OFF_ACCF   154368                  // uchar[512]       512
#define OFF_GHIST  154880                  // int[128]         512
#define OFF_HIST2  155392                  // int[256]        1024
#define OFF_SC     156416                  // int[128]         512
#define OFF_STAGEB 156928                  // float[20][688]  55040 (phase-P only)
#define SMEM_BYTES (156928 + 55040 + 16)

__global__ __launch_bounds__(NT, 1)
void detect_kernel(const float* __restrict__ loc,
                   const float* __restrict__ conf,
                   const float* __restrict__ prior,
                   float* __restrict__ out) {
    extern __shared__ unsigned char smem_raw[];
    ull*           skey   = (ull*)(smem_raw + OFF_SKEY);
    float4*        clist  = (float4*)(smem_raw + OFF_CLIST);
    float*         stageA = (float*)(smem_raw + OFF_CLIST);       // phase-P alias
    float*         stageB = (float*)(smem_raw + OFF_STAGEB);      // phase-P only
    float4*        pfbox  = (float4*)(smem_raw + OFF_PFBOX);
    ull*           chA    = (ull*)(smem_raw + OFF_CHA);
    ull*           chB    = (ull*)(smem_raw + OFF_CHB);
    int*           whist  = (int*)(smem_raw + OFF_CHA);           // [20][128] alias (10240 <= 12288)
    unsigned char* accf   = (unsigned char*)(smem_raw + OFF_ACCF);
    int*           ghist  = (int*)(smem_raw + OFF_GHIST);
    int*           hist2  = (int*)(smem_raw + OFF_HIST2);
    int*           sc     = (int*)(smem_raw + OFF_SC);
    int*           wcnt   = sc + 16;    // 20
    int*           wbase  = sc + 48;    // 20
    int*           ccount = sc + 80;    // 20: per-class accepted (persists)
    ull*           slimit = (ull*)(smem_raw + OFF_SC + 480);

    const int b    = blockIdx.x;
    const int tid  = threadIdx.x;
    const int wid  = tid >> 5;
    const int lane = tid & 31;
    const size_t base = (size_t)b * NP;
    const unsigned full = 0xffffffffu;
    float* outb = out + (size_t)b * (TOPK * 6);

    // ================= Phase P: pipelined softmax/argmax ===================
    for (int q = lane; q < NBIN; q += 32) whist[wid * NBIN + q] = 0;
    __syncwarp();

    {
        float* bufs[2] = { stageA + wid * 688, stageB + wid * 688 };
        unsigned bufs_s32[2];
        bufs_s32[0] = (unsigned)__cvta_generic_to_shared(bufs[0]);
        bufs_s32[1] = (unsigned)__cvta_generic_to_shared(bufs[1]);
        const int ng = (NGRP - wid + NW - 1) / NW;   // groups this warp owns

        // prologue: issue group 0
        {
            int g = wid;
            int e0 = g * 32;
            int nrows = NP - e0; if (nrows > 32) nrows = 32;
            int nflt4 = (nrows * NC + 3) >> 2;
            const float4* src = (const float4*)(conf + (base + (size_t)e0) * NC);
#pragma unroll
            for (int q = 0; q < 6; q++) {
                int o4 = q * 32 + lane;
                if (o4 < nflt4) CP_ASYNC_16(bufs_s32[0] + o4 * 16, src + o4);
            }
        }
        CP_ASYNC_COMMIT();

        for (int i = 0; i < ng; i++) {
            // issue next group into the other buffer
            if (i + 1 < ng) {
                int gn = wid + NW * (i + 1);
                int e0n = gn * 32;
                int nrowsn = NP - e0n; if (nrowsn > 32) nrowsn = 32;
                int nflt4n = (nrowsn * NC + 3) >> 2;
                const float4* srcn = (const float4*)(conf + (base + (size_t)e0n) * NC);
                unsigned dst = bufs_s32[(i + 1) & 1];
#pragma unroll
                for (int q = 0; q < 6; q++) {
                    int o4 = q * 32 + lane;
                    if (o4 < nflt4n) CP_ASYNC_16(dst + o4 * 16, srcn + o4);
                }
            }
            CP_ASYNC_COMMIT();
            CP_ASYNC_WAIT_1();                 // group i data resident
            __syncwarp();

            int g = wid + NW * i;
            int e0 = g * 32;
            int nrows = NP - e0; if (nrows > 32) nrows = 32;
            float* stage = bufs[i & 1];

            ull key = 0; int bin = -1; bool val = false;
            if (lane < nrows) {
                int e = e0 + lane;
                float c[NC];
#pragma unroll
                for (int q = 0; q < NC; q++) c[q] = stage[lane * NC + q];
                float m = c[0];
#pragma unroll
                for (int q = 1; q < NC; q++) m = fmaxf(m, c[q]);
                float sum = 0.0f;
#pragma unroll
                for (int q = 0; q < NC; q++) sum += expf(c[q] - m);
                float bm = c[1]; int bc = 1;
#pragma unroll
                for (int q = 2; q < NC; q++) {
                    if (c[q] > bm) { bm = c[q]; bc = q; }
                }
                float score = expf(bm - m) / sum;
                float ms = (score > 0.01f) ? score : -1.0f;
                key = pack_key(ms, (unsigned)e, (unsigned)(bc - 1));
                skey[e] = key;
                bin = (int)(key >> 51) - BIN0;
                val = (bin >= 0) && (bin < NBIN);
            }
            int mbin = val ? bin : -1;
            unsigned mm = __match_any_sync(full, mbin);
            if (val && lane == (__ffs(mm) - 1)) whist[wid * NBIN + mbin] += __popc(mm);
            __syncwarp();
        }
        CP_ASYNC_WAIT_0();
    }
    if (tid < 20) ccount[tid] = 0;
    if (tid == 0) { sc[1] = 0; *slimit = ~0ull; }
    __syncthreads();

    // reduce per-warp hists
    if (tid < NBIN) {
        int a2 = 0;
#pragma unroll
        for (int w = 0; w < NW; w++) a2 += whist[w * NBIN + tid];
        ghist[tid] = a2;
    }
    __syncthreads();

    // ================= Phase S: rounds (normally 1) ========================
    for (int round = 0; round < 16; round++) {
        ull limit = *slimit;

        if (round > 0) {
            for (int q = lane; q < NBIN; q += 32) whist[wid * NBIN + q] = 0;
            __syncwarp();
            for (int i = 0; i < KPL; i++) {
                int e = tid + i * NT;
                ull k = (e < NP) ? skey[e] : 0ull;
                int bin = (int)(k >> 51) - BIN0;
                bool val = (e < NP) && (k < limit) && (bin >= 0) && (bin < NBIN);
                int mbin = val ? bin : -1;
                unsigned mm = __match_any_sync(full, mbin);
                if (val && lane == (__ffs(mm) - 1)) whist[wid * NBIN + mbin] += __popc(mm);
            }
            __syncthreads();
            if (tid < NBIN) {
                int a2 = 0;
#pragma unroll
                for (int w = 0; w < NW; w++) a2 += whist[w * NBIN + tid];
                ghist[tid] = a2;
            }
            __syncthreads();
        }

        // ---- suffix-scan threshold select (warp 0) ----
        if (wid == 0) {
            if (lane == 0) { sc[0] = 0; sc[3] = 0; sc[5] = 0; sc[6] = 0; sc[9] = 0; }
            __syncwarp();
            int c0 = ghist[lane * 4], c1 = ghist[lane * 4 + 1];
            int c2 = ghist[lane * 4 + 2], c3 = ghist[lane * 4 + 3];
            int s = c0 + c1 + c2 + c3;
            int suf = s;
#pragma unroll
            for (int o = 1; o < 32; o <<= 1) {
                int tt = __shfl_down_sync(full, suf, o);
                if (lane + o < 32) suf += tt;
            }
            int total = __shfl_sync(full, suf, 0);
            int cum = suf - s;
            int T = -1, A = 0, S = 0;
            if (cum < WANT && cum + c3 >= WANT) { T = lane * 4 + 3; A = cum; S = cum + c3; }
            cum += c3;
            if (T < 0 && cum < WANT && cum + c2 >= WANT) { T = lane * 4 + 2; A = cum; S = cum + c2; }
            cum += c2;
            if (T < 0 && cum < WANT && cum + c1 >= WANT) { T = lane * 4 + 1; A = cum; S = cum + c1; }
            cum += c1;
            if (T < 0 && cum < WANT && cum + c0 >= WANT) { T = lane * 4;     A = cum; S = cum + c0; }
            if (T >= 0) { sc[0] = T; sc[3] = A; sc[5] = S; }
            if (lane == 0 && total < WANT) { sc[6] = 1; sc[0] = 0; sc[3] = 0; sc[5] = total; }
        }
        __syncthreads();

        // ---- 8-bit refinement if boundary bin overflows chunk capacity ----
        if (sc[5] > CHCAP && !sc[6]) {
            if (tid < 256) hist2[tid] = 0;
            __syncthreads();
            int Tc = BIN0 + sc[0];
            for (int i = 0; i < KPL; i++) {
                int e = tid + i * NT;
                if (e < NP) {
                    ull k = skey[e];
                    if (k < limit && (int)(k >> 51) == Tc)
                        atomicAdd(&hist2[(int)((k >> 43) & 0xFF)], 1);
                }
            }
            __syncthreads();
            if (wid == 0) {
                int cc[8], s = 0;
#pragma unroll
                for (int q = 0; q < 8; q++) { cc[q] = hist2[lane * 8 + q]; s += cc[q]; }
                int suf = s;
#pragma unroll
                for (int o = 1; o < 32; o <<= 1) {
                    int tt = __shfl_down_sync(full, suf, o);
                    if (lane + o < 32) suf += tt;
                }
                int want2 = WANT - sc[3];
                int cum = suf - s;
                int T2 = -1;
#pragma unroll
                for (int q = 7; q >= 0; q--) {
                    if (T2 < 0 && cum < want2 && cum + cc[q] >= want2) T2 = lane * 8 + q;
                    cum += cc[q];
                }
                if (T2 >= 0) { sc[8] = T2; sc[9] = 1; }
            }
            __syncthreads();
        }
        ull thk = ((ull)(BIN0 + sc[0]) << 51);
        if (sc[9]) thk |= ((ull)sc[8] << 43);

        // ---- atomic-free scan-gather from smem keys ----
        {
            int cnt = 0;
#pragma unroll
            for (int i = 0; i < KPL; i++) {
                int e = tid + i * NT;
                ull k = (e < NP) ? skey[e] : 0ull;
                cnt += ((k >= thk) && (k < limit)) ? 1 : 0;
            }
            int wsum = cnt;
#pragma unroll
            for (int o = 16; o > 0; o >>= 1) wsum += __shfl_xor_sync(full, wsum, o);
            if (lane == 0) wcnt[wid] = wsum;
        }
        __syncthreads();
        if (wid == 0) {
            int v = (lane < NW) ? wcnt[lane] : 0;
            int x = v;
#pragma unroll
            for (int o = 1; o < 32; o <<= 1) {
                int t2 = __shfl_up_sync(full, x, o);
                if (lane >= o) x += t2;
            }
            if (lane < NW) wbase[lane] = x - v;
            if (lane == NW - 1) sc[7] = x;
        }
        __syncthreads();
        {
            int off = wbase[wid];
#pragma unroll
            for (int i = 0; i < KPL; i++) {
                int e = tid + i * NT;
                ull k = (e < NP) ? skey[e] : 0ull;
                bool cnd = (k >= thk) && (k < limit);
                unsigned mm = __ballot_sync(full, cnd);
                if (cnd) {
                    int pos = off + __popc(mm & ((1u << lane) - 1u));
                    if (pos < CHCAP) chA[pos] = k;
                }
                off += __popc(mm);
            }
        }
        __syncthreads();
        int Sg = sc[7]; if (Sg > CHCAP) Sg = CHCAP;
        if (Sg == 0) break;

        // ---- block bitonic sort (descending), P2 <= 512, 1 elem/thread ----
        int P2 = 64; while (P2 < Sg) P2 <<= 1;
        for (int q = Sg + tid; q < P2; q += NT) chA[q] = 0ull;
        __syncthreads();
        {
            ull v = (tid < P2) ? chA[tid] : 0ull;
            ull* bufs2[2] = { chA, chB };  // contiguous scratch: OOB lands in-region
            int pb = 1;
            for (int k = 2; k <= P2; k <<= 1) {
                int j = k >> 1;
                for (; j >= 32; j >>= 1) {
                    bufs2[pb][tid] = v;
                    __syncthreads();
                    ull o = bufs2[pb][tid ^ j];
                    pb ^= 1;
                    bool keepmax = ((tid & k) == 0) == ((tid & j) == 0);
                    v = keepmax ? (v > o ? v : o) : (v > o ? o : v);
                }
                for (; j > 0; j >>= 1) {
                    ull o = __shfl_xor_sync(full, v, j);
                    bool keepmax = ((tid & k) == 0) == ((tid & j) == 0);
                    v = keepmax ? (v > o ? v : o) : (v > o ? o : v);
                }
            }
            __syncthreads();
            if (tid < P2) chA[tid] = v;
        }
        if (tid < CHCAP) accf[tid] = 0;
        __syncthreads();

        // ---- deferred box decode for the sorted candidates ----
        if (tid < Sg) {
            ull k = chA[tid];
            int idx = (int)((~(unsigned)(k >> 16)) & 0xFFFFu);
            float4 l  = ((const float4*)loc)[base + idx];
            float4 pr = ((const float4*)prior)[idx];
            float cx = pr.x + l.x * 0.1f * pr.z;
            float cy = pr.y + l.y * 0.1f * pr.w;
            float w  = pr.z * expf(l.z * 0.2f);
            float h  = pr.w * expf(l.w * 0.2f);
            pfbox[tid] = make_float4(cx - w * 0.5f, cy - h * 0.5f,
                                     cx + w * 0.5f, cy + h * 0.5f);
        }
        __syncthreads();

        // ---- 20 parallel per-class greedy walks over the sorted chunk ----
        {
            int ncR = ccount[wid];
            for (int r0 = 0; r0 < Sg && ncR < CCAP; r0 += 32) {
                int rem = Sg - r0; if (rem > 32) rem = 32;
                ull k = (lane < rem) ? chA[r0 + lane] : 0ull;
                bool mine = (lane < rem) && (((int)(k >> 8) & 0xFF) == wid);
                unsigned mask = __ballot_sync(full, mine);
                while (mask && ncR < CCAP) {
                    int r = r0 + (__ffs(mask) - 1);
                    mask &= mask - 1;
                    float4 cb = pfbox[r];                 // uniform LDS.128
                    float car = (cb.z - cb.x) * (cb.w - cb.y);
                    bool hit = false;
                    for (int q0 = 0; q0 < ncR; q0 += 32) {
                        int q = q0 + lane;
                        if (q < ncR) {
                            float4 ab = clist[wid * CCAP + q];
                            float ix1 = fmaxf(ab.x, cb.x), iy1 = fmaxf(ab.y, cb.y);
                            float ix2 = fminf(ab.z, cb.z), iy2 = fminf(ab.w, cb.w);
                            float inter = fmaxf(ix2 - ix1, 0.f) * fmaxf(iy2 - iy1, 0.f);
                            float ar = (ab.z - ab.x) * (ab.w - ab.y);
                            if (inter / (ar + car - inter) > 0.45f) hit = true;
                        }
                    }
                    if (!__any_sync(full, hit)) {
                        if (lane == 0) { clist[wid * CCAP + ncR] = cb; accf[r] = 1; }
                        ncR++;
                        __syncwarp();
                    }
                }
            }
            if (lane == 0) ccount[wid] = ncR;
        }
        __syncthreads();

        // ---- ordered compaction + emit (atomic-free; Sg <= 512 < NT) ----
        bool f = (tid < Sg) && accf[tid];
        unsigned bal = __ballot_sync(full, f);
        if (lane == 0) wcnt[wid] = __popc(bal);
        __syncthreads();
        if (wid == 0) {
            int v = (lane < NW) ? wcnt[lane] : 0;
            int x = v;
#pragma unroll
            for (int o = 1; o < 32; o <<= 1) {
                int t2 = __shfl_up_sync(full, x, o);
                if (lane >= o) x += t2;
            }
            if (lane < NW) wbase[lane] = x - v;
            if (lane == NW - 1) sc[10] = x;
        }
        __syncthreads();
        int nout = sc[1];
        if (f) {
            int pos = nout + wbase[wid] + __popc(bal & ((1u << lane) - 1u));
            if (pos < TOPK) {
                ull k = chA[tid];
                float4 cb = pfbox[tid];
                float* orow = outb + pos * 6;
                orow[0] = cb.x; orow[1] = cb.y; orow[2] = cb.z; orow[3] = cb.w;
                orow[4] = __uint_as_float(((unsigned)(k >> 32)) ^ 0x80000000u);
                orow[5] = (float)((int)(k >> 8) & 0xFF);
            }
        }
        __syncthreads();
        if (tid == 0) {
            int rem = TOPK - nout;
            int na = (sc[10] < rem) ? sc[10] : rem;
            sc[1] = nout + na;
            *slimit = thk;
            sc[15] = sc[6];
        }
        __syncthreads();
        if (sc[1] >= TOPK || sc[15]) break;
    }

    // ---- zero-fill remaining rows ----
    int nout = sc[1];
    for (int q = nout * 6 + tid; q < TOPK * 6; q += NT) outb[q] = 0.0f;
}

// ---------------------------------------------------------------------------
extern "C" void kernel_launch(void* const* d_in, const int* in_sizes, int n_in,
                              void* d_out, int out_size) {
    const float* loc   = (const float*)d_in[0];
    const float* conf  = (const float*)d_in[1];
    const float* prior = (const float*)d_in[2];
    float* out = (float*)d_out;

    cudaFuncSetAttribute(detect_kernel,
                         cudaFuncAttributeMaxDynamicSharedMemorySize,
                         SMEM_BYTES);

    detect_kernel<<<NB, NT, SMEM_BYTES>>>(loc, conf, prior, out);
}

// round 16
// speedup vs baseline: 1.0788x; 1.0788x over previous
#include <cuda_runtime.h>
#include <cstdint>
#include <cfloat>

typedef unsigned long long ull;

// Problem constants
#define NB   128
#define NP   8732
#define NC   21
#define TOPK 200
#define NT   640
#define NW   20
#define KPL  14                  // ceil(8732 / 640)

// Select config
#define BIN0  6016
#define NBIN  128
#define CHCAP 512
#define WANT  384
#define CCAP  200

// Global scratch. g_hist: written by prep (atomics), read+zeroed by select
// every launch -> zero at the start of every graph replay.
__device__ ull g_keys[NB * NP];
__device__ int g_hist[NB * NBIN];

// key = [monotone score:32][~idx:16][cls:8][0:8]; unsigned MAX == (score desc, idx asc)
__device__ __forceinline__ ull pack_key(float v, unsigned idx, unsigned cls) {
    unsigned bq = __float_as_uint(v);
    bq ^= (unsigned)(((int)bq >> 31) | 0x80000000);
    return ((ull)bq << 32) | ((ull)((~idx) & 0xFFFFu) << 16) | ((ull)cls << 8);
}

#define CP_ASYNC_16(dst_s32, src_g) \
    asm volatile("cp.async.cg.shared.global [%0], [%1], 16;" :: "r"(dst_s32), "l"(src_g))
#define CP_ASYNC_COMMIT() asm volatile("cp.async.commit_group;")
#define CP_ASYNC_WAIT_1() asm volatile("cp.async.wait_group 1;")
#define CP_ASYNC_WAIT_0() asm volatile("cp.async.wait_group 0;")

// ===========================================================================
// Kernel 1: single-wave pipelined softmax/argmax + per-batch histogram.
// 592 blocks x 8 warps (4 blocks/SM), each warp grid-strides ~7 groups of
// 32 rows with double-buffered cp.async. All groups are exactly 32 rows.
// ===========================================================================
#define K1_THREADS 256
#define K1_WPB     8
#define NGROUPS    ((NB * NP) / 32)          // 34928 exactly
#define K1_BLOCKS  592                       // 148 * 4 -> single wave
#define K1_WARPS   (K1_BLOCKS * K1_WPB)      // 4736

__global__ __launch_bounds__(K1_THREADS, 4)
void prep_kernel(const float* __restrict__ conf) {
    __shared__ float stage[2][K1_WPB][688];  // 672 used + pad
    const int wid  = threadIdx.x >> 5;
    const int lane = threadIdx.x & 31;
    const unsigned full = 0xffffffffu;
    const int wg = blockIdx.x * K1_WPB + wid;

    unsigned s32[2];
    s32[0] = (unsigned)__cvta_generic_to_shared(&stage[0][wid][0]);
    s32[1] = (unsigned)__cvta_generic_to_shared(&stage[1][wid][0]);
    const int ng = (NGROUPS - wg + K1_WARPS - 1) / K1_WARPS;   // >=1 (wg < 4736 < NGROUPS)

    // prologue: issue group 0
    {
        const float4* src = (const float4*)(conf + (size_t)wg * 32 * NC);
#pragma unroll
        for (int q = 0; q < 6; q++) {
            int o4 = q * 32 + lane;
            if (o4 < 168) CP_ASYNC_16(s32[0] + o4 * 16, src + o4);
        }
    }
    CP_ASYNC_COMMIT();

    for (int i = 0; i < ng; i++) {
        if (i + 1 < ng) {
            size_t gn = (size_t)(wg + (i + 1) * K1_WARPS);
            const float4* srcn = (const float4*)(conf + gn * 32 * NC);
            unsigned dst = s32[(i + 1) & 1];
#pragma unroll
            for (int q = 0; q < 6; q++) {
                int o4 = q * 32 + lane;
                if (o4 < 168) CP_ASYNC_16(dst + o4 * 16, srcn + o4);
            }
        }
        CP_ASYNC_COMMIT();
        CP_ASYNC_WAIT_1();                 // group i resident
        __syncwarp();

        int g = wg + i * K1_WARPS;
        int e = g * 32 + lane;
        const float* st = &stage[i & 1][wid][0];

        float c[NC];
#pragma unroll
        for (int q = 0; q < NC; q++) c[q] = st[lane * NC + q];  // stride 21: conflict-free

        float m = c[0];
#pragma unroll
        for (int q = 1; q < NC; q++) m = fmaxf(m, c[q]);
        float sum = 0.0f;
#pragma unroll
        for (int q = 0; q < NC; q++) sum += expf(c[q] - m);
        float bm = c[1]; int bc = 1;
#pragma unroll
        for (int q = 2; q < NC; q++) {
            if (c[q] > bm) { bm = c[q]; bc = q; }
        }
        float score = expf(bm - m) / sum;
        float ms = (score > 0.01f) ? score : -1.0f;

        int bidx = e / NP;
        int p = e - bidx * NP;
        ull key = pack_key(ms, (unsigned)p, (unsigned)(bc - 1));
        g_keys[e] = key;

        int bin = (int)(key >> 51) - BIN0;
        bool val = (bin >= 0) && (bin < NBIN);
        int slot = val ? (bidx * NBIN + bin) : -1;
        unsigned mm = __match_any_sync(full, slot);
        if (val && lane == (__ffs(mm) - 1)) atomicAdd(&g_hist[slot], __popc(mm));
        __syncwarp();
    }
    CP_ASYNC_WAIT_0();
}

// ===========================================================================
// Kernel 2 (640 threads = 20 warps): threshold + atomic-free scan-gather +
// 512-wide block sort + deferred box decode + per-class walks + emit.
// (byte-identical to R12)
// ===========================================================================
// smem byte offsets
#define OFF_CHA    0                         // ull[512]        4096
#define OFF_CHB    4096                      // ull[1024]       8192  (sort scratch; tid up to 639)
#define OFF_PFBOX  12288                     // float4[512]     8192  (whist on refill: 20*128 ints)
#define OFF_CLIST  20480                     // float4[20*200] 64000
#define OFF_ACCF   84480                     // uchar[512]       512
#define OFF_GHIST  84992                     // int[128]         512
#define OFF_HIST2  85504                     // int[256]        1024
#define OFF_SC     86528                     // int[128]         512
#define SMEM_BYTES (87040 + 16)

__global__ __launch_bounds__(NT, 1)
void select_kernel(const float* __restrict__ loc,
                   const float* __restrict__ prior,
                   float* __restrict__ out) {
    extern __shared__ unsigned char smem_raw[];
    ull*           chA    = (ull*)(smem_raw + OFF_CHA);
    ull*           chB    = (ull*)(smem_raw + OFF_CHB);
    float4*        pfbox  = (float4*)(smem_raw + OFF_PFBOX);
    float4*        clist  = (float4*)(smem_raw + OFF_CLIST);
    unsigned char* accf   = (unsigned char*)(smem_raw + OFF_ACCF);
    int*           ghist  = (int*)(smem_raw + OFF_GHIST);
    int*           hist2  = (int*)(smem_raw + OFF_HIST2);
    int*           sc     = (int*)(smem_raw + OFF_SC);
    int*           wcnt   = sc + 16;    // 20
    int*           wbase  = sc + 48;    // 20
    int*           ccount = sc + 80;    // 20: per-class accepted (persists)
    ull*           slimit = (ull*)(smem_raw + OFF_SC + 480);

    const int b    = blockIdx.x;
    const int tid  = threadIdx.x;
    const int wid  = tid >> 5;
    const int lane = tid & 31;
    const size_t base = (size_t)b * NP;
    const unsigned full = 0xffffffffu;
    float* outb = out + (size_t)b * (TOPK * 6);

    if (tid < NBIN) {
        ghist[tid] = g_hist[b * NBIN + tid];
        g_hist[b * NBIN + tid] = 0;
    }
    if (tid < 20) ccount[tid] = 0;
    if (tid == 0) { sc[1] = 0; *slimit = ~0ull; }
    __syncthreads();

    for (int round = 0; round < 16; round++) {
        ull limit = *slimit;

        // rounds >= 1: rebuild histogram (whist aliases pfbox region)
        if (round > 0) {
            int* whist = (int*)pfbox + wid * NBIN;
            for (int q = lane; q < NBIN; q += 32) whist[q] = 0;
            __syncwarp();
            for (int i = 0; i < KPL; i++) {
                int e = tid + i * NT;
                ull k = (e < NP) ? g_keys[base + e] : 0ull;
                int bin = (int)(k >> 51) - BIN0;
                bool val = (e < NP) && (k < limit) && (bin >= 0) && (bin < NBIN);
                int mbin = val ? bin : -1;
                unsigned mm = __match_any_sync(full, mbin);
                if (val && lane == (__ffs(mm) - 1)) whist[mbin] += __popc(mm);
            }
            __syncthreads();
            if (tid < NBIN) {
                int a2 = 0;
                int* wh = (int*)pfbox;
#pragma unroll
                for (int w = 0; w < NW; w++) a2 += wh[w * NBIN + tid];
                ghist[tid] = a2;
            }
            __syncthreads();
        }

        // ---- suffix-scan threshold select (warp 0) ----
        if (wid == 0) {
            if (lane == 0) { sc[0] = 0; sc[3] = 0; sc[5] = 0; sc[6] = 0; sc[9] = 0; }
            __syncwarp();
            int c0 = ghist[lane * 4], c1 = ghist[lane * 4 + 1];
            int c2 = ghist[lane * 4 + 2], c3 = ghist[lane * 4 + 3];
            int s = c0 + c1 + c2 + c3;
            int suf = s;
#pragma unroll
            for (int o = 1; o < 32; o <<= 1) {
                int tt = __shfl_down_sync(full, suf, o);
                if (lane + o < 32) suf += tt;
            }
            int total = __shfl_sync(full, suf, 0);
            int cum = suf - s;
            int T = -1, A = 0, S = 0;
            if (cum < WANT && cum + c3 >= WANT) { T = lane * 4 + 3; A = cum; S = cum + c3; }
            cum += c3;
            if (T < 0 && cum < WANT && cum + c2 >= WANT) { T = lane * 4 + 2; A = cum; S = cum + c2; }
            cum += c2;
            if (T < 0 && cum < WANT && cum + c1 >= WANT) { T = lane * 4 + 1; A = cum; S = cum + c1; }
            cum += c1;
            if (T < 0 && cum < WANT && cum + c0 >= WANT) { T = lane * 4;     A = cum; S = cum + c0; }
            if (T >= 0) { sc[0] = T; sc[3] = A; sc[5] = S; }
            if (lane == 0 && total < WANT) { sc[6] = 1; sc[0] = 0; sc[3] = 0; sc[5] = total; }
        }
        __syncthreads();

        // ---- 8-bit refinement if boundary bin overflows chunk capacity ----
        if (sc[5] > CHCAP && !sc[6]) {
            if (tid < 256) hist2[tid] = 0;
            __syncthreads();
            int Tc = BIN0 + sc[0];
            for (int i = 0; i < KPL; i++) {
                int e = tid + i * NT;
                if (e < NP) {
                    ull k = g_keys[base + e];
                    if (k < limit && (int)(k >> 51) == Tc)
                        atomicAdd(&hist2[(int)((k >> 43) & 0xFF)], 1);
                }
            }
            __syncthreads();
            if (wid == 0) {
                int cc[8], s = 0;
#pragma unroll
                for (int q = 0; q < 8; q++) { cc[q] = hist2[lane * 8 + q]; s += cc[q]; }
                int suf = s;
#pragma unroll
                for (int o = 1; o < 32; o <<= 1) {
                    int tt = __shfl_down_sync(full, suf, o);
                    if (lane + o < 32) suf += tt;
                }
                int want2 = WANT - sc[3];
                int cum = suf - s;
                int T2 = -1;
#pragma unroll
                for (int q = 7; q >= 0; q--) {
                    if (T2 < 0 && cum < want2 && cum + cc[q] >= want2) T2 = lane * 8 + q;
                    cum += cc[q];
                }
                if (T2 >= 0) { sc[8] = T2; sc[9] = 1; }
            }
            __syncthreads();
        }
        ull thk = ((ull)(BIN0 + sc[0]) << 51);
        if (sc[9]) thk |= ((ull)sc[8] << 43);

        // ---- atomic-free scan-gather ----
        ull kv[KPL]; bool cnd[KPL];
        int cnt = 0;
#pragma unroll
        for (int i = 0; i < KPL; i++) {
            int e = tid + i * NT;
            kv[i] = (e < NP) ? g_keys[base + e] : 0ull;
            cnd[i] = (kv[i] >= thk) && (kv[i] < limit);
            cnt += cnd[i] ? 1 : 0;
        }
        {
            int wsum = cnt;
#pragma unroll
            for (int o = 16; o > 0; o >>= 1) wsum += __shfl_xor_sync(full, wsum, o);
            if (lane == 0) wcnt[wid] = wsum;
        }
        __syncthreads();
        if (wid == 0) {
            int v = (lane < NW) ? wcnt[lane] : 0;
            int x = v;
#pragma unroll
            for (int o = 1; o < 32; o <<= 1) {
                int t2 = __shfl_up_sync(full, x, o);
                if (lane >= o) x += t2;
            }
            if (lane < NW) wbase[lane] = x - v;
            if (lane == NW - 1) sc[7] = x;
        }
        __syncthreads();
        {
            int off = wbase[wid];
#pragma unroll
            for (int i = 0; i < KPL; i++) {
                unsigned mm = __ballot_sync(full, cnd[i]);
                if (cnd[i]) {
                    int pos = off + __popc(mm & ((1u << lane) - 1u));
                    if (pos < CHCAP) chA[pos] = kv[i];
                }
                off += __popc(mm);
            }
        }
        __syncthreads();
        int Sg = sc[7]; if (Sg > CHCAP) Sg = CHCAP;
        if (Sg == 0) break;

        // ---- block bitonic sort (descending), P2 <= 512, 1 elem/thread ----
        int P2 = 64; while (P2 < Sg) P2 <<= 1;
        for (int q = Sg + tid; q < P2; q += NT) chA[q] = 0ull;
        __syncthreads();
        {
            ull v = (tid < P2) ? chA[tid] : 0ull;
            ull* bufs[2] = { chA, chB };   // chB sized for tid<640 writes
            int pb = 1;                    // start in chB (chA holds live data)
            for (int k = 2; k <= P2; k <<= 1) {
                int j = k >> 1;
                for (; j >= 32; j >>= 1) {
                    bufs[pb][tid] = v;
                    __syncthreads();
                    ull o = bufs[pb][tid ^ j];
                    pb ^= 1;
                    bool keepmax = ((tid & k) == 0) == ((tid & j) == 0);
                    v = keepmax ? (v > o ? v : o) : (v > o ? o : v);
                }
                for (; j > 0; j >>= 1) {
                    ull o = __shfl_xor_sync(full, v, j);
                    bool keepmax = ((tid & k) == 0) == ((tid & j) == 0);
                    v = keepmax ? (v > o ? v : o) : (v > o ? o : v);
                }
            }
            __syncthreads();
            if (tid < P2) chA[tid] = v;
        }
        if (tid < CHCAP) accf[tid] = 0;
        __syncthreads();

        // ---- deferred box decode for the sorted candidates ----
        if (tid < Sg) {
            ull k = chA[tid];
            int idx = (int)((~(unsigned)(k >> 16)) & 0xFFFFu);
            float4 l  = ((const float4*)loc)[base + idx];
            float4 pr = ((const float4*)prior)[idx];
            float cx = pr.x + l.x * 0.1f * pr.z;
            float cy = pr.y + l.y * 0.1f * pr.w;
            float w  = pr.z * expf(l.z * 0.2f);
            float h  = pr.w * expf(l.w * 0.2f);
            pfbox[tid] = make_float4(cx - w * 0.5f, cy - h * 0.5f,
                                     cx + w * 0.5f, cy + h * 0.5f);
        }
        __syncthreads();

        // ---- 20 parallel per-class greedy walks over the sorted chunk ----
        {
            int ncR = ccount[wid];
            for (int r0 = 0; r0 < Sg && ncR < CCAP; r0 += 32) {
                int rem = Sg - r0; if (rem > 32) rem = 32;
                ull k = (lane < rem) ? chA[r0 + lane] : 0ull;
                bool mine = (lane < rem) && (((int)(k >> 8) & 0xFF) == wid);
                unsigned mask = __ballot_sync(full, mine);
                while (mask && ncR < CCAP) {
                    int r = r0 + (__ffs(mask) - 1);
                    mask &= mask - 1;
                    float4 cb = pfbox[r];                 // uniform LDS.128
                    float car = (cb.z - cb.x) * (cb.w - cb.y);
                    bool hit = false;
                    for (int q0 = 0; q0 < ncR; q0 += 32) {
                        int q = q0 + lane;
                        if (q < ncR) {
                            float4 ab = clist[wid * CCAP + q];
                            float ix1 = fmaxf(ab.x, cb.x), iy1 = fmaxf(ab.y, cb.y);
                            float ix2 = fminf(ab.z, cb.z), iy2 = fminf(ab.w, cb.w);
                            float inter = fmaxf(ix2 - ix1, 0.f) * fmaxf(iy2 - iy1, 0.f);
                            float ar = (ab.z - ab.x) * (ab.w - ab.y);
                            if (inter / (ar + car - inter) > 0.45f) hit = true;
                        }
                    }
                    if (!__any_sync(full, hit)) {
                        if (lane == 0) { clist[wid * CCAP + ncR] = cb; accf[r] = 1; }
                        ncR++;
                        __syncwarp();
                    }
                }
            }
            if (lane == 0) ccount[wid] = ncR;
        }
        __syncthreads();

        // ---- ordered compaction + emit (atomic-free; Sg <= 512 < NT) ----
        bool f = (tid < Sg) && accf[tid];
        unsigned bal = __ballot_sync(full, f);
        if (lane == 0) wcnt[wid] = __popc(bal);
        __syncthreads();
        if (wid == 0) {
            int v = (lane < NW) ? wcnt[lane] : 0;
            int x = v;
#pragma unroll
            for (int o = 1; o < 32; o <<= 1) {
                int t2 = __shfl_up_sync(full, x, o);
                if (lane >= o) x += t2;
            }
            if (lane < NW) wbase[lane] = x - v;
            if (lane == NW - 1) sc[10] = x;
        }
        __syncthreads();
        int nout = sc[1];
        if (f) {
            int pos = nout + wbase[wid] + __popc(bal & ((1u << lane) - 1u));
            if (pos < TOPK) {
                ull k = chA[tid];
                float4 cb = pfbox[tid];
                float* orow = outb + pos * 6;
                orow[0] = cb.x; orow[1] = cb.y; orow[2] = cb.z; orow[3] = cb.w;
                orow[4] = __uint_as_float(((unsigned)(k >> 32)) ^ 0x80000000u);
                orow[5] = (float)((int)(k >> 8) & 0xFF);
            }
        }
        __syncthreads();
        if (tid == 0) {
            int rem = TOPK - nout;
            int na = (sc[10] < rem) ? sc[10] : rem;
            sc[1] = nout + na;
            *slimit = thk;
            sc[15] = sc[6];
        }
        __syncthreads();
        if (sc[1] >= TOPK || sc[15]) break;
    }

    // ---- zero-fill remaining rows ----
    int nout = sc[1];
    for (int q = nout * 6 + tid; q < TOPK * 6; q += NT) outb[q] = 0.0f;
}

// ---------------------------------------------------------------------------
extern "C" void kernel_launch(void* const* d_in, const int* in_sizes, int n_in,
                              void* d_out, int out_size) {
    const float* loc   = (const float*)d_in[0];
    const float* conf  = (const float*)d_in[1];
    const float* prior = (const float*)d_in[2];
    float* out = (float*)d_out;

    cudaFuncSetAttribute(select_kernel,
                         cudaFuncAttributeMaxDynamicSharedMemorySize,
                         SMEM_BYTES);

    prep_kernel<<<K1_BLOCKS, K1_THREADS>>>(conf);
    select_kernel<<<NB, NT, SMEM_BYTES>>>(loc, prior, out);
}

// round 17
// speedup vs baseline: 1.2882x; 1.1941x over previous
#include <cuda_runtime.h>
#include <cstdint>
#include <cfloat>

typedef unsigned long long ull;

// Problem constants
#define NB   128
#define NP   8732
#define NC   21
#define TOPK 200
#define NT   640
#define NW   20
#define KPL  14                  // ceil(8732 / 640)

// Select config
#define BIN0  6016
#define NBIN  128
#define CHCAP 512
#define WANT  248
#define CCAP  200

// Global scratch. g_hist: written by prep (atomics), read+zeroed by select
// every launch -> zero at the start of every graph replay.
__device__ ull g_keys[NB * NP];
__device__ int g_hist[NB * NBIN];

// key = [monotone score:32][~idx:16][cls:8][0:8]; unsigned MAX == (score desc, idx asc)
__device__ __forceinline__ ull pack_key(float v, unsigned idx, unsigned cls) {
    unsigned bq = __float_as_uint(v);
    bq ^= (unsigned)(((int)bq >> 31) | 0x80000000);
    return ((ull)bq << 32) | ((ull)((~idx) & 0xFFFFu) << 16) | ((ull)cls << 8);
}

#define CP_ASYNC_16(dst_s32, src_g) \
    asm volatile("cp.async.cg.shared.global [%0], [%1], 16;" :: "r"(dst_s32), "l"(src_g))
#define CP_ASYNC_COMMIT() asm volatile("cp.async.commit_group;")
#define CP_ASYNC_WAIT_1() asm volatile("cp.async.wait_group 1;")
#define CP_ASYNC_WAIT_0() asm volatile("cp.async.wait_group 0;")

// ===========================================================================
// Kernel 1: single-wave pipelined softmax/argmax + per-batch histogram.
// (unchanged from R15)
// ===========================================================================
#define K1_THREADS 256
#define K1_WPB     8
#define NGROUPS    ((NB * NP) / 32)          // 34928 exactly
#define K1_BLOCKS  592                       // 148 * 4 -> single wave
#define K1_WARPS   (K1_BLOCKS * K1_WPB)      // 4736

__global__ __launch_bounds__(K1_THREADS, 4)
void prep_kernel(const float* __restrict__ conf) {
    __shared__ float stage[2][K1_WPB][688];  // 672 used + pad
    const int wid  = threadIdx.x >> 5;
    const int lane = threadIdx.x & 31;
    const unsigned full = 0xffffffffu;
    const int wg = blockIdx.x * K1_WPB + wid;

    unsigned s32[2];
    s32[0] = (unsigned)__cvta_generic_to_shared(&stage[0][wid][0]);
    s32[1] = (unsigned)__cvta_generic_to_shared(&stage[1][wid][0]);
    const int ng = (NGROUPS - wg + K1_WARPS - 1) / K1_WARPS;

    {
        const float4* src = (const float4*)(conf + (size_t)wg * 32 * NC);
#pragma unroll
        for (int q = 0; q < 6; q++) {
            int o4 = q * 32 + lane;
            if (o4 < 168) CP_ASYNC_16(s32[0] + o4 * 16, src + o4);
        }
    }
    CP_ASYNC_COMMIT();

    for (int i = 0; i < ng; i++) {
        if (i + 1 < ng) {
            size_t gn = (size_t)(wg + (i + 1) * K1_WARPS);
            const float4* srcn = (const float4*)(conf + gn * 32 * NC);
            unsigned dst = s32[(i + 1) & 1];
#pragma unroll
            for (int q = 0; q < 6; q++) {
                int o4 = q * 32 + lane;
                if (o4 < 168) CP_ASYNC_16(dst + o4 * 16, srcn + o4);
            }
        }
        CP_ASYNC_COMMIT();
        CP_ASYNC_WAIT_1();
        __syncwarp();

        int g = wg + i * K1_WARPS;
        int e = g * 32 + lane;
        const float* st = &stage[i & 1][wid][0];

        float c[NC];
#pragma unroll
        for (int q = 0; q < NC; q++) c[q] = st[lane * NC + q];

        float m = c[0];
#pragma unroll
        for (int q = 1; q < NC; q++) m = fmaxf(m, c[q]);
        float sum = 0.0f;
#pragma unroll
        for (int q = 0; q < NC; q++) sum += expf(c[q] - m);
        float bm = c[1]; int bc = 1;
#pragma unroll
        for (int q = 2; q < NC; q++) {
            if (c[q] > bm) { bm = c[q]; bc = q; }
        }
        float score = expf(bm - m) / sum;
        float ms = (score > 0.01f) ? score : -1.0f;

        int bidx = e / NP;
        int p = e - bidx * NP;
        ull key = pack_key(ms, (unsigned)p, (unsigned)(bc - 1));
        g_keys[e] = key;

        int bin = (int)(key >> 51) - BIN0;
        bool val = (bin >= 0) && (bin < NBIN);
        int slot = val ? (bidx * NBIN + bin) : -1;
        unsigned mm = __match_any_sync(full, slot);
        if (val && lane == (__ffs(mm) - 1)) atomicAdd(&g_hist[slot], __popc(mm));
        __syncwarp();
    }
    CP_ASYNC_WAIT_0();
}

// ===========================================================================
// Kernel 2 (640 threads = 20 warps): register-resident keys + threshold +
// refine-to-256 + scan-gather + <=256-wide sort + walks + emit.
// ===========================================================================
// smem byte offsets
#define OFF_CHA    0                         // ull[512]        4096
#define OFF_CHB    4096                      // ull[1024]       8192  (sort scratch; tid up to 639)
#define OFF_PFBOX  12288                     // float4[512]     8192  (whist on refill: 20*128 ints)
#define OFF_CLIST  20480                     // float4[20*200] 64000
#define OFF_ACCF   84480                     // uchar[512]       512
#define OFF_GHIST  84992                     // int[128]         512
#define OFF_HIST2  85504                     // int[256]        1024
#define OFF_SC     86528                     // int[128]         512
#define SMEM_BYTES (87040 + 16)

__global__ __launch_bounds__(NT, 1)
void select_kernel(const float* __restrict__ loc,
                   const float* __restrict__ prior,
                   float* __restrict__ out) {
    extern __shared__ unsigned char smem_raw[];
    ull*           chA    = (ull*)(smem_raw + OFF_CHA);
    ull*           chB    = (ull*)(smem_raw + OFF_CHB);
    float4*        pfbox  = (float4*)(smem_raw + OFF_PFBOX);
    float4*        clist  = (float4*)(smem_raw + OFF_CLIST);
    unsigned char* accf   = (unsigned char*)(smem_raw + OFF_ACCF);
    int*           ghist  = (int*)(smem_raw + OFF_GHIST);
    int*           hist2  = (int*)(smem_raw + OFF_HIST2);
    int*           sc     = (int*)(smem_raw + OFF_SC);
    int*           wcnt   = sc + 16;    // 20
    int*           wbase  = sc + 48;    // 20
    int*           ccount = sc + 80;    // 20: per-class accepted (persists)
    ull*           slimit = (ull*)(smem_raw + OFF_SC + 480);

    const int b    = blockIdx.x;
    const int tid  = threadIdx.x;
    const int wid  = tid >> 5;
    const int lane = tid & 31;
    const size_t base = (size_t)b * NP;
    const unsigned full = 0xffffffffu;
    float* outb = out + (size_t)b * (TOPK * 6);

    if (tid < NBIN) {
        ghist[tid] = g_hist[b * NBIN + tid];
        g_hist[b * NBIN + tid] = 0;
    }
    if (tid < 20) ccount[tid] = 0;
    if (tid == 0) { sc[1] = 0; *slimit = ~0ull; }

    // ---- load this thread's keys once (keys never change across rounds) ----
    ull kv[KPL];
#pragma unroll
    for (int i = 0; i < KPL; i++) {
        int e = tid + i * NT;
        kv[i] = (e < NP) ? g_keys[base + e] : 0ull;
    }
    __syncthreads();

    for (int round = 0; round < 16; round++) {
        ull limit = *slimit;

        // rounds >= 1: rebuild histogram from registers (whist aliases pfbox)
        if (round > 0) {
            int* whist = (int*)pfbox + wid * NBIN;
            for (int q = lane; q < NBIN; q += 32) whist[q] = 0;
            __syncwarp();
#pragma unroll
            for (int i = 0; i < KPL; i++) {
                ull k = kv[i];
                int bin = (int)(k >> 51) - BIN0;
                bool val = (k < limit) && (bin >= 0) && (bin < NBIN);
                int mbin = val ? bin : -1;
                unsigned mm = __match_any_sync(full, mbin);
                if (val && lane == (__ffs(mm) - 1)) whist[mbin] += __popc(mm);
            }
            __syncthreads();
            if (tid < NBIN) {
                int a2 = 0;
                int* wh = (int*)pfbox;
#pragma unroll
                for (int w = 0; w < NW; w++) a2 += wh[w * NBIN + tid];
                ghist[tid] = a2;
            }
            __syncthreads();
        }

        // ---- suffix-scan threshold select (warp 0) ----
        if (wid == 0) {
            if (lane == 0) { sc[0] = 0; sc[3] = 0; sc[5] = 0; sc[6] = 0; sc[9] = 0; }
            __syncwarp();
            int c0 = ghist[lane * 4], c1 = ghist[lane * 4 + 1];
            int c2 = ghist[lane * 4 + 2], c3 = ghist[lane * 4 + 3];
            int s = c0 + c1 + c2 + c3;
            int suf = s;
#pragma unroll
            for (int o = 1; o < 32; o <<= 1) {
                int tt = __shfl_down_sync(full, suf, o);
                if (lane + o < 32) suf += tt;
            }
            int total = __shfl_sync(full, suf, 0);
            int cum = suf - s;
            int T = -1, A = 0, S = 0;
            if (cum < WANT && cum + c3 >= WANT) { T = lane * 4 + 3; A = cum; S = cum + c3; }
            cum += c3;
            if (T < 0 && cum < WANT && cum + c2 >= WANT) { T = lane * 4 + 2; A = cum; S = cum + c2; }
            cum += c2;
            if (T < 0 && cum < WANT && cum + c1 >= WANT) { T = lane * 4 + 1; A = cum; S = cum + c1; }
            cum += c1;
            if (T < 0 && cum < WANT && cum + c0 >= WANT) { T = lane * 4;     A = cum; S = cum + c0; }
            if (T >= 0) { sc[0] = T; sc[3] = A; sc[5] = S; }
            if (lane == 0 && total < WANT) { sc[6] = 1; sc[0] = 0; sc[3] = 0; sc[5] = total; }
        }
        __syncthreads();

        // ---- 8-bit refinement whenever the chunk would exceed 256 ----
        if (sc[5] > 256 && !sc[6]) {
            if (tid < 256) hist2[tid] = 0;
            __syncthreads();
            int Tc = BIN0 + sc[0];
#pragma unroll
            for (int i = 0; i < KPL; i++) {
                ull k = kv[i];
                if (k < limit && (int)(k >> 51) == Tc)
                    atomicAdd(&hist2[(int)((k >> 43) & 0xFF)], 1);
            }
            __syncthreads();
            if (wid == 0) {
                int cc[8], s = 0;
#pragma unroll
                for (int q = 0; q < 8; q++) { cc[q] = hist2[lane * 8 + q]; s += cc[q]; }
                int suf = s;
#pragma unroll
                for (int o = 1; o < 32; o <<= 1) {
                    int tt = __shfl_down_sync(full, suf, o);
                    if (lane + o < 32) suf += tt;
                }
                int want2 = WANT - sc[3];
                int cum = suf - s;
                int T2 = -1;
#pragma unroll
                for (int q = 7; q >= 0; q--) {
                    if (T2 < 0 && cum < want2 && cum + cc[q] >= want2) T2 = lane * 8 + q;
                    cum += cc[q];
                }
                if (T2 >= 0) { sc[8] = T2; sc[9] = 1; }
            }
            __syncthreads();
        }
        ull thk = ((ull)(BIN0 + sc[0]) << 51);
        if (sc[9]) thk |= ((ull)sc[8] << 43);

        // ---- atomic-free scan-gather from registers ----
        bool cnd[KPL];
        int cnt = 0;
#pragma unroll
        for (int i = 0; i < KPL; i++) {
            cnd[i] = (kv[i] >= thk) && (kv[i] < limit);
            cnt += cnd[i] ? 1 : 0;
        }
        {
            int wsum = cnt;
#pragma unroll
            for (int o = 16; o > 0; o >>= 1) wsum += __shfl_xor_sync(full, wsum, o);
            if (lane == 0) wcnt[wid] = wsum;
        }
        __syncthreads();
        if (wid == 0) {
            int v = (lane < NW) ? wcnt[lane] : 0;
            int x = v;
#pragma unroll
            for (int o = 1; o < 32; o <<= 1) {
                int t2 = __shfl_up_sync(full, x, o);
                if (lane >= o) x += t2;
            }
            if (lane < NW) wbase[lane] = x - v;
            if (lane == NW - 1) sc[7] = x;
        }
        __syncthreads();
        {
            int off = wbase[wid];
#pragma unroll
            for (int i = 0; i < KPL; i++) {
                unsigned mm = __ballot_sync(full, cnd[i]);
                if (cnd[i]) {
                    int pos = off + __popc(mm & ((1u << lane) - 1u));
                    if (pos < CHCAP) chA[pos] = kv[i];
                }
                off += __popc(mm);
            }
        }
        __syncthreads();
        int Sg = sc[7]; if (Sg > CHCAP) Sg = CHCAP;
        if (Sg == 0) break;

        // ---- block bitonic sort (descending), P2 <= 512 (usually 256) ----
        int P2 = 64; while (P2 < Sg) P2 <<= 1;
        for (int q = Sg + tid; q < P2; q += NT) chA[q] = 0ull;
        __syncthreads();
        {
            ull v = (tid < P2) ? chA[tid] : 0ull;
            ull* bufs[2] = { chA, chB };
            int pb = 1;
            for (int k = 2; k <= P2; k <<= 1) {
                int j = k >> 1;
                for (; j >= 32; j >>= 1) {
                    bufs[pb][tid] = v;
                    __syncthreads();
                    ull o = bufs[pb][tid ^ j];
                    pb ^= 1;
                    bool keepmax = ((tid & k) == 0) == ((tid & j) == 0);
                    v = keepmax ? (v > o ? v : o) : (v > o ? o : v);
                }
                for (; j > 0; j >>= 1) {
                    ull o = __shfl_xor_sync(full, v, j);
                    bool keepmax = ((tid & k) == 0) == ((tid & j) == 0);
                    v = keepmax ? (v > o ? v : o) : (v > o ? o : v);
                }
            }
            __syncthreads();
            if (tid < P2) chA[tid] = v;
        }
        if (tid < CHCAP) accf[tid] = 0;
        __syncthreads();

        // ---- deferred box decode for the sorted candidates ----
        if (tid < Sg) {
            ull k = chA[tid];
            int idx = (int)((~(unsigned)(k >> 16)) & 0xFFFFu);
            float4 l  = ((const float4*)loc)[base + idx];
            float4 pr = ((const float4*)prior)[idx];
            float cx = pr.x + l.x * 0.1f * pr.z;
            float cy = pr.y + l.y * 0.1f * pr.w;
            float w  = pr.z * expf(l.z * 0.2f);
            float h  = pr.w * expf(l.w * 0.2f);
            pfbox[tid] = make_float4(cx - w * 0.5f, cy - h * 0.5f,
                                     cx + w * 0.5f, cy + h * 0.5f);
        }
        __syncthreads();

        // ---- 20 parallel per-class greedy walks over the sorted chunk ----
        {
            int ncR = ccount[wid];
            for (int r0 = 0; r0 < Sg && ncR < CCAP; r0 += 32) {
                int rem = Sg - r0; if (rem > 32) rem = 32;
                ull k = (lane < rem) ? chA[r0 + lane] : 0ull;
                bool mine = (lane < rem) && (((int)(k >> 8) & 0xFF) == wid);
                unsigned mask = __ballot_sync(full, mine);
                while (mask && ncR < CCAP) {
                    int r = r0 + (__ffs(mask) - 1);
                    mask &= mask - 1;
                    float4 cb = pfbox[r];                 // uniform LDS.128
                    float car = (cb.z - cb.x) * (cb.w - cb.y);
                    bool hit = false;
                    for (int q0 = 0; q0 < ncR; q0 += 32) {
                        int q = q0 + lane;
                        if (q < ncR) {
                            float4 ab = clist[wid * CCAP + q];
                            float ix1 = fmaxf(ab.x, cb.x), iy1 = fmaxf(ab.y, cb.y);
                            float ix2 = fminf(ab.z, cb.z), iy2 = fminf(ab.w, cb.w);
                            float inter = fmaxf(ix2 - ix1, 0.f) * fmaxf(iy2 - iy1, 0.f);
                            float ar = (ab.z - ab.x) * (ab.w - ab.y);
                            if (inter / (ar + car - inter) > 0.45f) hit = true;
                        }
                    }
                    if (!__any_sync(full, hit)) {
                        if (lane == 0) { clist[wid * CCAP + ncR] = cb; accf[r] = 1; }
                        ncR++;
                        __syncwarp();
                    }
                }
            }
            if (lane == 0) ccount[wid] = ncR;
        }
        __syncthreads();

        // ---- ordered compaction + emit (atomic-free; Sg <= 512 < NT) ----
        bool f = (tid < Sg) && accf[tid];
        unsigned bal = __ballot_sync(full, f);
        if (lane == 0) wcnt[wid] = __popc(bal);
        __syncthreads();
        if (wid == 0) {
            int v = (lane < NW) ? wcnt[lane] : 0;
            int x = v;
#pragma unroll
            for (int o = 1; o < 32; o <<= 1) {
                int t2 = __shfl_up_sync(full, x, o);
                if (lane >= o) x += t2;
            }
            if (lane < NW) wbase[lane] = x - v;
            if (lane == NW - 1) sc[10] = x;
        }
        __syncthreads();
        int nout = sc[1];
        if (f) {
            int pos = nout + wbase[wid] + __popc(bal & ((1u << lane) - 1u));
            if (pos < TOPK) {
                ull k = chA[tid];
                float4 cb = pfbox[tid];
                float* orow = outb + pos * 6;
                orow[0] = cb.x; orow[1] = cb.y; orow[2] = cb.z; orow[3] = cb.w;
                orow[4] = __uint_as_float(((unsigned)(k >> 32)) ^ 0x80000000u);
                orow[5] = (float)((int)(k >> 8) & 0xFF);
            }
        }
        __syncthreads();
        if (tid == 0) {
            int rem = TOPK - nout;
            int na = (sc[10] < rem) ? sc[10] : rem;
            sc[1] = nout + na;
            *slimit = thk;
            sc[15] = sc[6];
        }
        __syncthreads();
        if (sc[1] >= TOPK || sc[15]) break;
    }

    // ---- zero-fill remaining rows ----
    int nout = sc[1];
    for (int q = nout * 6 + tid; q < TOPK * 6; q += NT) outb[q] = 0.0f;
}

// ---------------------------------------------------------------------------
extern "C" void kernel_launch(void* const* d_in, const int* in_sizes, int n_in,
                              void* d_out, int out_size) {
    const float* loc   = (const float*)d_in[0];
    const float* conf  = (const float*)d_in[1];
    const float* prior = (const float*)d_in[2];
    float* out = (float*)d_out;

    cudaFuncSetAttribute(select_kernel,
                         cudaFuncAttributeMaxDynamicSharedMemorySize,
                         SMEM_BYTES);

    prep_kernel<<<K1_BLOCKS, K1_THREADS>>>(conf);
    select_kernel<<<NB, NT, SMEM_BYTES>>>(loc, prior, out);
}